// round 5
// baseline (speedup 1.0000x reference)
#include <cuda_runtime.h>
#include <cuda_bf16.h>

// ---------------- problem constants (fixed shapes per reference) -------------
#define NMAX   50000
#define EMAX   1250000
#define GMAX   1024
#define LD     32      // label/embedding dim
#define HD     64      // hidden dim

// ---------------- device scratch (no allocation allowed) --------------------
__device__ float g_h0 [NMAX * LD];   // embedded labels
__device__ float g_z0 [NMAX * LD];   // layer0: h + sum(neigh)
__device__ float g_h1 [NMAX * HD];   // layer0 output h
__device__ float g_z1 [NMAX * HD];   // layer1: h + sum(neigh)
__device__ float g_a  [NMAX * HD];   // MLP intermediate
__device__ float g_sum[GMAX * HD];   // per-graph feature sums
__device__ float g_cnt[GMAX];        // per-graph node counts
__device__ int   g_deg[NMAX];        // in-degree histogram / placement cursor
__device__ int   g_rowp[NMAX + 1];   // CSR row pointers (by dst)
__device__ int   g_csr [EMAX];       // src node ids grouped by dst

// ---------------- init: embedding lookup + zero accumulators/hist -----------
__global__ void init_kernel(const int* __restrict__ labels,
                            const float* __restrict__ emb,
                            int n, int g, int max_label,
                            float* __restrict__ h0,
                            float* __restrict__ sums, float* __restrict__ cnts,
                            int* __restrict__ deg)
{
    int idx = blockIdx.x * blockDim.x + threadIdx.x;
    if (idx < n * LD) {
        int node = idx >> 5;
        int d    = idx & (LD - 1);
        int lab  = labels[node];
        lab = lab < 0 ? 0 : (lab > max_label ? max_label : lab);
        h0[idx]  = emb[lab * LD + d];
    }
    if (idx < n)      deg[idx]  = 0;
    if (idx < g * HD) sums[idx] = 0.f;
    if (idx < g)      cnts[idx] = 0.f;
}

// ---------------- CSR build: histogram -> scan -> place ---------------------
__global__ void hist_kernel(const int* __restrict__ dst, int* __restrict__ deg, int E)
{
    int e = blockIdx.x * blockDim.x + threadIdx.x;
    if (e < E) atomicAdd(&deg[dst[e]], 1);
}

__global__ void scan_kernel(const int* __restrict__ deg,
                            int* __restrict__ rowp, int* __restrict__ cursor, int n)
{
    __shared__ int sh[1024];
    int t = threadIdx.x;
    int chunk = (n + 1023) >> 10;
    int beg = t * chunk;
    int end = min(n, beg + chunk);
    int s = 0;
    for (int i = beg; i < end; i++) s += deg[i];
    sh[t] = s;
    __syncthreads();
    for (int off = 1; off < 1024; off <<= 1) {
        int v = (t >= off) ? sh[t - off] : 0;
        __syncthreads();
        sh[t] += v;
        __syncthreads();
    }
    int run = sh[t] - s;             // exclusive prefix of this chunk
    for (int i = beg; i < end; i++) {
        rowp[i]   = run;
        cursor[i] = run;
        run += deg[i];
    }
    if (t == 1023) rowp[n] = sh[1023];
}

__global__ void place_kernel(const int* __restrict__ src, const int* __restrict__ dst,
                             int* __restrict__ cursor, int* __restrict__ csr, int E)
{
    int e = blockIdx.x * blockDim.x + threadIdx.x;
    if (e >= E) return;
    int pos = atomicAdd(&cursor[dst[e]], 1);
    csr[pos] = src[e];
}

// ---------------- gather: z[v] = h[v] + sum_{s in N_in(v)} h[s] -------------
// Warp per node; lane covers 1 (DIM=32) or 2 (DIM=64) feature columns.
// Neighbor ids loaded 32-at-a-time, broadcast via shfl; h row reads coalesced.
template <int DIM>
__global__ void __launch_bounds__(256)
gather_kernel(const float* __restrict__ h,
              const int* __restrict__ rowp, const int* __restrict__ csr,
              float* __restrict__ z, int n)
{
    int warp = (blockIdx.x * blockDim.x + threadIdx.x) >> 5;
    int lane = threadIdx.x & 31;
    if (warp >= n) return;
    const int v = warp;
    int beg = rowp[v];
    int end = rowp[v + 1];

    float a0 = h[(size_t)v * DIM + lane];
    float a1 = (DIM == 64) ? h[(size_t)v * DIM + 32 + lane] : 0.f;

    for (int base = beg; base < end; base += 32) {
        int m = end - base; if (m > 32) m = 32;
        int idx = (lane < m) ? csr[base + lane] : 0;
        for (int j = 0; j < m; j++) {
            int s = __shfl_sync(0xFFFFFFFFu, idx, j);
            a0 += h[(size_t)s * DIM + lane];
            if (DIM == 64) a1 += h[(size_t)s * DIM + 32 + lane];
        }
    }
    z[(size_t)v * DIM + lane] = a0;
    if (DIM == 64) z[(size_t)v * DIM + 32 + lane] = a1;
}

// ---------------- register-tiled GEMM half-layer ----------------------------
// out[64-node tile, 64 feats] = relu(bias + x @ W)   (W: [K][64] row-major)
// 128 threads; thread = 4 nodes x 8 features.
// POOL: atomically accumulate relu result into per-graph sums (+ counts).
template <int K, bool POOL>
__global__ void __launch_bounds__(128)
gemm_kernel(const float* __restrict__ x1,
            const float* __restrict__ W, const float* __restrict__ bias,
            float* __restrict__ out,
            const int* __restrict__ gids,
            float* __restrict__ sums, float* __restrict__ cnts, int n)
{
    const int XP = 68;
    __shared__ float Xs[K * XP];
    __shared__ float Ws[K * HD];
    __shared__ float bs[HD];

    const int tid = threadIdx.x;
    const int node_base = blockIdx.x * 64;

    {
        const float4* Wg = reinterpret_cast<const float4*>(W);
        float4* Wsm4 = reinterpret_cast<float4*>(Ws);
#pragma unroll
        for (int i = tid; i < K * HD / 4; i += 128) Wsm4[i] = Wg[i];
    }
    if (tid < HD) bs[tid] = bias[tid];

#pragma unroll
    for (int i = tid; i < 64 * (K / 4); i += 128) {
        int nn = i & 63;
        int kc = i >> 6;
        int node = node_base + nn;
        float4 v = make_float4(0.f, 0.f, 0.f, 0.f);
        if (node < n)
            v = *reinterpret_cast<const float4*>(x1 + (size_t)node * K + kc * 4);
        Xs[(kc * 4 + 0) * XP + nn] = v.x;
        Xs[(kc * 4 + 1) * XP + nn] = v.y;
        Xs[(kc * 4 + 2) * XP + nn] = v.z;
        Xs[(kc * 4 + 3) * XP + nn] = v.w;
    }
    __syncthreads();

    const int tn = tid & 15;
    const int tf = tid >> 4;

    float acc[4][8];
#pragma unroll
    for (int i = 0; i < 4; i++)
#pragma unroll
        for (int j = 0; j < 8; j++) acc[i][j] = bs[tf * 8 + j];

#pragma unroll 8
    for (int k = 0; k < K; k++) {
        float4 xv = *reinterpret_cast<const float4*>(Xs + k * XP + tn * 4);
        float4 wa = *reinterpret_cast<const float4*>(Ws + k * HD + tf * 8);
        float4 wb = *reinterpret_cast<const float4*>(Ws + k * HD + tf * 8 + 4);
        const float xs[4] = {xv.x, xv.y, xv.z, xv.w};
        const float ws[8] = {wa.x, wa.y, wa.z, wa.w, wb.x, wb.y, wb.z, wb.w};
#pragma unroll
        for (int i = 0; i < 4; i++)
#pragma unroll
            for (int j = 0; j < 8; j++) acc[i][j] += xs[i] * ws[j];
    }

#pragma unroll
    for (int i = 0; i < 4; i++) {
        int node = node_base + tn * 4 + i;
        if (node >= n) continue;
        float4 ra = make_float4(fmaxf(acc[i][0], 0.f), fmaxf(acc[i][1], 0.f),
                                fmaxf(acc[i][2], 0.f), fmaxf(acc[i][3], 0.f));
        float4 rb = make_float4(fmaxf(acc[i][4], 0.f), fmaxf(acc[i][5], 0.f),
                                fmaxf(acc[i][6], 0.f), fmaxf(acc[i][7], 0.f));
        if (!POOL) {
            float* o = out + (size_t)node * HD + tf * 8;
            *reinterpret_cast<float4*>(o)     = ra;
            *reinterpret_cast<float4*>(o + 4) = rb;
        } else {
            int g = gids[node];
            float* sg = sums + (size_t)g * HD + tf * 8;
            atomicAdd(reinterpret_cast<float4*>(sg),     ra);
            atomicAdd(reinterpret_cast<float4*>(sg + 4), rb);
            if (tf == 0) atomicAdd(&cnts[g], 1.0f);
        }
    }
}

// ---------------- scorer: out[g] = relu(mean_h @ sw1 + sb1) @ sw2 + sb2 -----
__global__ void scorer_kernel(const float* __restrict__ sums,
                              const float* __restrict__ cnts,
                              const float* __restrict__ sw1,
                              const float* __restrict__ sb1,
                              const float* __restrict__ sw2,
                              const float* __restrict__ sb2,
                              float* __restrict__ out)
{
    int g = blockIdx.x;
    int f = threadIdx.x;           // 64 threads
    float cnt = fmaxf(cnts[g], 1.0f);
    float inv = 1.0f / cnt;
    float acc = sb1[f];
    const float* sg = sums + (size_t)g * HD;
    for (int k = 0; k < HD; k++) acc += (sg[k] * inv) * sw1[k * HD + f];
    float hf = fmaxf(acc, 0.f) * sw2[f];

    __shared__ float red[HD];
    red[f] = hf;
    __syncthreads();
    if (f < 32) red[f] += red[f + 32];
    __syncthreads();
    if (f < 32) {
        float v = red[f];
#pragma unroll
        for (int off = 16; off > 0; off >>= 1)
            v += __shfl_down_sync(0xFFFFFFFFu, v, off);
        if (f == 0) out[g] = v + sb2[0];
    }
}

// ---------------- launcher --------------------------------------------------
extern "C" void kernel_launch(void* const* d_in, const int* in_sizes, int n_in,
                              void* d_out, int out_size)
{
    const int*   labels = (const int*)  d_in[0];
    const int*   src    = (const int*)  d_in[1];
    const int*   dst    = (const int*)  d_in[2];
    const int*   gids   = (const int*)  d_in[3];
    const float* emb    = (const float*)d_in[4];
    const float* w1_0   = (const float*)d_in[5];
    const float* b1_0   = (const float*)d_in[6];
    const float* w2_0   = (const float*)d_in[7];
    const float* b2_0   = (const float*)d_in[8];
    const float* w1_1   = (const float*)d_in[9];
    const float* b1_1   = (const float*)d_in[10];
    const float* w2_1   = (const float*)d_in[11];
    const float* b2_1   = (const float*)d_in[12];
    const float* sw1    = (const float*)d_in[13];
    const float* sb1    = (const float*)d_in[14];
    const float* sw2    = (const float*)d_in[15];
    const float* sb2    = (const float*)d_in[16];
    float* out = (float*)d_out;

    int N = in_sizes[0];
    int E = in_sizes[1];
    int G = out_size;
    int max_label = in_sizes[4] / LD - 1;

    if (N > NMAX) N = NMAX;
    if (E > EMAX) E = EMAX;
    if (G > GMAX) G = GMAX;

    float *h0, *z0, *h1, *z1, *a, *sums, *cnts;
    int *deg, *rowp, *csr;
    cudaGetSymbolAddress((void**)&h0,   g_h0);
    cudaGetSymbolAddress((void**)&z0,   g_z0);
    cudaGetSymbolAddress((void**)&h1,   g_h1);
    cudaGetSymbolAddress((void**)&z1,   g_z1);
    cudaGetSymbolAddress((void**)&a,    g_a);
    cudaGetSymbolAddress((void**)&sums, g_sum);
    cudaGetSymbolAddress((void**)&cnts, g_cnt);
    cudaGetSymbolAddress((void**)&deg,  g_deg);
    cudaGetSymbolAddress((void**)&rowp, g_rowp);
    cudaGetSymbolAddress((void**)&csr,  g_csr);

    const int TB = 256;
    const int NB = (N + 63) / 64;            // GEMM node tiles
    const int GB = (N + 7) / 8;              // gather blocks (8 warps)

    // 1. embedding + zero (sums, cnts, deg)
    init_kernel<<<(N * LD + TB - 1) / TB, TB>>>(labels, emb, N, G, max_label,
                                                h0, sums, cnts, deg);
    // 2. CSR build (shared by both layers)
    hist_kernel<<<(E + TB - 1) / TB, TB>>>(dst, deg, E);
    scan_kernel<<<1, 1024>>>(deg, rowp, deg, N);     // deg becomes placement cursor
    place_kernel<<<(E + TB - 1) / TB, TB>>>(src, dst, deg, csr, E);
    // 3. layer0: gather + MLP
    gather_kernel<LD><<<GB, 256>>>(h0, rowp, csr, z0, N);
    gemm_kernel<LD, false><<<NB, 128>>>(z0, w1_0, b1_0, a,  nullptr, nullptr, nullptr, N);
    gemm_kernel<HD, false><<<NB, 128>>>(a,  w2_0, b2_0, h1, nullptr, nullptr, nullptr, N);
    // 4. layer1: gather + MLP + fused mean-pool
    gather_kernel<HD><<<GB, 256>>>(h1, rowp, csr, z1, N);
    gemm_kernel<HD, false><<<NB, 128>>>(z1, w1_1, b1_1, a, nullptr, nullptr, nullptr, N);
    gemm_kernel<HD, true ><<<NB, 128>>>(a,  w2_1, b2_1, nullptr, gids, sums, cnts, N);
    // 5. scorer
    scorer_kernel<<<G, HD>>>(sums, cnts, sw1, sb1, sw2, sb2, out);
}

// round 6
// speedup vs baseline: 1.2782x; 1.2782x over previous
#include <cuda_runtime.h>
#include <cuda_bf16.h>

typedef unsigned long long ull;

// ---------------- problem constants (fixed shapes per reference) -------------
#define NMAX   50000
#define EMAX   1250000
#define GMAX   1024
#define LD     32      // label/embedding dim
#define HD     64      // hidden dim

// ---------------- device scratch (no allocation allowed) --------------------
__device__ float g_h0 [NMAX * LD];   // embedded labels
__device__ float g_ag0[NMAX * LD];   // layer0 aggregation
__device__ float g_h1 [NMAX * HD];   // layer0 output h
__device__ float g_ag1[NMAX * HD];   // layer1 aggregation
__device__ float g_a  [NMAX * HD];   // MLP intermediate
__device__ float g_sum[GMAX * HD];   // per-graph feature sums
__device__ float g_cnt[GMAX];        // per-graph node counts

// ---------------- packed f32x2 helpers (Blackwell FFMA2) --------------------
__device__ __forceinline__ void fma2(ull& acc, ull a, ull b) {
    asm("fma.rn.f32x2 %0, %1, %2, %0;" : "+l"(acc) : "l"(a), "l"(b));
}
__device__ __forceinline__ ull pack_dup(float x) {
    ull r;
    asm("mov.b64 %0, {%1, %1};" : "=l"(r) : "r"(__float_as_uint(x)));
    return r;
}
__device__ __forceinline__ float2 unpack2(ull v) {
    unsigned lo, hi;
    asm("mov.b64 {%0, %1}, %2;" : "=r"(lo), "=r"(hi) : "l"(v));
    return make_float2(__uint_as_float(lo), __uint_as_float(hi));
}

// ---------------- init: embedding lookup + zero all accumulators ------------
__global__ void init_kernel(const int* __restrict__ labels,
                            const float* __restrict__ emb,
                            int n, int g, int max_label,
                            float* __restrict__ h0, float* __restrict__ ag0,
                            float* __restrict__ ag1,
                            float* __restrict__ sums, float* __restrict__ cnts)
{
    int idx = blockIdx.x * blockDim.x + threadIdx.x;
    if (idx < n * LD) {
        int node = idx >> 5;
        int d    = idx & (LD - 1);
        int lab  = labels[node];
        lab = lab < 0 ? 0 : (lab > max_label ? max_label : lab);
        h0[idx]  = emb[lab * LD + d];
        ag0[idx] = 0.f;
    }
    if (idx < n * HD) ag1[idx] = 0.f;
    if (idx < g * HD) sums[idx] = 0.f;
    if (idx < g)      cnts[idx] = 0.f;
}

// ---------------- edge scatter: agg[dst] += h[src] (vector atomics) ---------
template <int DIM>
__global__ void scatter_kernel(const int* __restrict__ src,
                               const int* __restrict__ dst,
                               const float* __restrict__ h,
                               float* __restrict__ agg, int E)
{
    const int J = DIM / 4;
    int idx = blockIdx.x * blockDim.x + threadIdx.x;
    if (idx >= E * J) return;
    int e = idx / J;
    int j = idx - e * J;
    int s = __ldg(&src[e]);
    int d = __ldg(&dst[e]);
    float4 v = *reinterpret_cast<const float4*>(h + (size_t)s * DIM + j * 4);
    atomicAdd(reinterpret_cast<float4*>(agg + (size_t)d * DIM + j * 4), v);
}

// ---------------- FFMA2 register-tiled GEMM half-layer ----------------------
// out[128-node tile, 64 feats] = relu(bias + (x1[+x2]) @ W)  (W: [K][64] row-major)
// 128 threads; thread = 8 nodes x 8 features as 8x4 packed f32x2 accumulators.
// Node groups per thread: {4*tn+i} and {64+4*tn+i} so both X LDS.128 are
// lane-contiguous (conflict-free). X staged in 32-k chunks (smem <= 33.5KB).
template <int K, bool ADD2, bool POOL>
__global__ void __launch_bounds__(128)
gemm_kernel(const float* __restrict__ x1, const float* __restrict__ x2,
            const float* __restrict__ W, const float* __restrict__ bias,
            float* __restrict__ out,
            const int* __restrict__ gids,
            float* __restrict__ sums, float* __restrict__ cnts, int n)
{
    const int XP = 132;                 // padded row pitch (floats) for Xs
    __shared__ float Xs[32 * XP];       // one 32-k chunk of X, transposed [k][node]
    __shared__ float Ws[K * HD];        // full W
    __shared__ float bs[HD];

    const int tid = threadIdx.x;
    const int node_base = blockIdx.x * 128;

    // stage W + bias once
    {
        const float4* Wg = reinterpret_cast<const float4*>(W);
        float4* Wsm4 = reinterpret_cast<float4*>(Ws);
#pragma unroll
        for (int i = tid; i < K * HD / 4; i += 128) Wsm4[i] = Wg[i];
    }
    if (tid < HD) bs[tid] = bias[tid];

    const int tn = tid & 15;            // node group (8 nodes, split 2x4)
    const int tf = tid >> 4;            // feature group (8 feats = 4 f32x2)

    ull acc[8][4];
    bool acc_init = false;

    for (int kc = 0; kc < K; kc += 32) {
        if (kc > 0) __syncthreads();    // protect Xs reuse
        // stage Xs[kk][node] for kk in [0,32): 128 nodes x 8 float4 chunks
#pragma unroll
        for (int i = tid; i < 128 * 8; i += 128) {
            int nn = i & 127;
            int c  = i >> 7;            // float4 chunk -> k offset c*4
            int node = node_base + nn;
            float4 v = make_float4(0.f, 0.f, 0.f, 0.f);
            if (node < n) {
                v = *reinterpret_cast<const float4*>(x1 + (size_t)node * K + kc + c * 4);
                if (ADD2) {
                    float4 u = *reinterpret_cast<const float4*>(x2 + (size_t)node * K + kc + c * 4);
                    v.x += u.x; v.y += u.y; v.z += u.z; v.w += u.w;
                }
            }
            Xs[(c * 4 + 0) * XP + nn] = v.x;
            Xs[(c * 4 + 1) * XP + nn] = v.y;
            Xs[(c * 4 + 2) * XP + nn] = v.z;
            Xs[(c * 4 + 3) * XP + nn] = v.w;
        }
        __syncthreads();

        if (!acc_init) {
            acc_init = true;
            ulonglong2 b01 = *reinterpret_cast<const ulonglong2*>(bs + tf * 8);
            ulonglong2 b23 = *reinterpret_cast<const ulonglong2*>(bs + tf * 8 + 4);
#pragma unroll
            for (int i = 0; i < 8; i++) {
                acc[i][0] = b01.x; acc[i][1] = b01.y;
                acc[i][2] = b23.x; acc[i][3] = b23.y;
            }
        }

#pragma unroll 8
        for (int kk = 0; kk < 32; kk++) {
            const float* xrow = Xs + kk * XP;
            float4 xa = *reinterpret_cast<const float4*>(xrow + tn * 4);
            float4 xb = *reinterpret_cast<const float4*>(xrow + 64 + tn * 4);
            const float* wrow = Ws + (kc + kk) * HD + tf * 8;
            ulonglong2 w01 = *reinterpret_cast<const ulonglong2*>(wrow);
            ulonglong2 w23 = *reinterpret_cast<const ulonglong2*>(wrow + 4);
            ull xd[8] = {pack_dup(xa.x), pack_dup(xa.y), pack_dup(xa.z), pack_dup(xa.w),
                         pack_dup(xb.x), pack_dup(xb.y), pack_dup(xb.z), pack_dup(xb.w)};
#pragma unroll
            for (int i = 0; i < 8; i++) {
                fma2(acc[i][0], xd[i], w01.x);
                fma2(acc[i][1], xd[i], w01.y);
                fma2(acc[i][2], xd[i], w23.x);
                fma2(acc[i][3], xd[i], w23.y);
            }
        }
    }

    // epilogue
#pragma unroll
    for (int i = 0; i < 8; i++) {
        int nn = (i < 4) ? (tn * 4 + i) : (64 + tn * 4 + (i - 4));
        int node = node_base + nn;
        if (node >= n) continue;
        float2 p0 = unpack2(acc[i][0]);
        float2 p1 = unpack2(acc[i][1]);
        float2 p2 = unpack2(acc[i][2]);
        float2 p3 = unpack2(acc[i][3]);
        float4 ra = make_float4(fmaxf(p0.x, 0.f), fmaxf(p0.y, 0.f),
                                fmaxf(p1.x, 0.f), fmaxf(p1.y, 0.f));
        float4 rb = make_float4(fmaxf(p2.x, 0.f), fmaxf(p2.y, 0.f),
                                fmaxf(p3.x, 0.f), fmaxf(p3.y, 0.f));
        if (!POOL) {
            float* o = out + (size_t)node * HD + tf * 8;
            *reinterpret_cast<float4*>(o)     = ra;
            *reinterpret_cast<float4*>(o + 4) = rb;
        } else {
            int g = gids[node];
            float* sg = sums + (size_t)g * HD + tf * 8;
            atomicAdd(reinterpret_cast<float4*>(sg),     ra);
            atomicAdd(reinterpret_cast<float4*>(sg + 4), rb);
            if (tf == 0) atomicAdd(&cnts[g], 1.0f);
        }
    }
}

// ---------------- scorer: out[g] = relu(mean_h @ sw1 + sb1) @ sw2 + sb2 -----
__global__ void scorer_kernel(const float* __restrict__ sums,
                              const float* __restrict__ cnts,
                              const float* __restrict__ sw1,
                              const float* __restrict__ sb1,
                              const float* __restrict__ sw2,
                              const float* __restrict__ sb2,
                              float* __restrict__ out)
{
    int g = blockIdx.x;
    int f = threadIdx.x;           // 64 threads
    float cnt = fmaxf(cnts[g], 1.0f);
    float inv = 1.0f / cnt;
    float acc = sb1[f];
    const float* sg = sums + (size_t)g * HD;
    for (int k = 0; k < HD; k++) acc += (sg[k] * inv) * sw1[k * HD + f];
    float hf = fmaxf(acc, 0.f) * sw2[f];

    __shared__ float red[HD];
    red[f] = hf;
    __syncthreads();
    if (f < 32) red[f] += red[f + 32];
    __syncthreads();
    if (f < 32) {
        float v = red[f];
#pragma unroll
        for (int off = 16; off > 0; off >>= 1)
            v += __shfl_down_sync(0xFFFFFFFFu, v, off);
        if (f == 0) out[g] = v + sb2[0];
    }
}

// ---------------- launcher --------------------------------------------------
extern "C" void kernel_launch(void* const* d_in, const int* in_sizes, int n_in,
                              void* d_out, int out_size)
{
    const int*   labels = (const int*)  d_in[0];
    const int*   src    = (const int*)  d_in[1];
    const int*   dst    = (const int*)  d_in[2];
    const int*   gids   = (const int*)  d_in[3];
    const float* emb    = (const float*)d_in[4];
    const float* w1_0   = (const float*)d_in[5];
    const float* b1_0   = (const float*)d_in[6];
    const float* w2_0   = (const float*)d_in[7];
    const float* b2_0   = (const float*)d_in[8];
    const float* w1_1   = (const float*)d_in[9];
    const float* b1_1   = (const float*)d_in[10];
    const float* w2_1   = (const float*)d_in[11];
    const float* b2_1   = (const float*)d_in[12];
    const float* sw1    = (const float*)d_in[13];
    const float* sb1    = (const float*)d_in[14];
    const float* sw2    = (const float*)d_in[15];
    const float* sb2    = (const float*)d_in[16];
    float* out = (float*)d_out;

    int N = in_sizes[0];
    int E = in_sizes[1];
    int G = out_size;
    int max_label = in_sizes[4] / LD - 1;

    if (N > NMAX) N = NMAX;
    if (E > EMAX) E = EMAX;
    if (G > GMAX) G = GMAX;

    float *h0, *ag0, *h1, *ag1, *a, *sums, *cnts;
    cudaGetSymbolAddress((void**)&h0,   g_h0);
    cudaGetSymbolAddress((void**)&ag0,  g_ag0);
    cudaGetSymbolAddress((void**)&h1,   g_h1);
    cudaGetSymbolAddress((void**)&ag1,  g_ag1);
    cudaGetSymbolAddress((void**)&a,    g_a);
    cudaGetSymbolAddress((void**)&sums, g_sum);
    cudaGetSymbolAddress((void**)&cnts, g_cnt);

    const int TB = 256;
    const int NB = (N + 127) / 128;   // GEMM node tiles

    // 1. embedding + zero accumulators
    init_kernel<<<(N * HD + TB - 1) / TB, TB>>>(labels, emb, N, G, max_label,
                                                h0, ag0, ag1, sums, cnts);
    // 2. layer0 scatter: ag0[dst] += h0[src]  (32-dim)
    scatter_kernel<LD><<<(E * (LD / 4) + TB - 1) / TB, TB>>>(src, dst, h0, ag0, E);
    // 3. layer0 MLP
    gemm_kernel<LD, true , false><<<NB, 128>>>(h0, ag0, w1_0, b1_0, a,  nullptr, nullptr, nullptr, N);
    gemm_kernel<HD, false, false><<<NB, 128>>>(a,  nullptr, w2_0, b2_0, h1, nullptr, nullptr, nullptr, N);
    // 4. layer1 scatter: ag1[dst] += h1[src]  (64-dim)
    scatter_kernel<HD><<<(E * (HD / 4) + TB - 1) / TB, TB>>>(src, dst, h1, ag1, E);
    // 5. layer1 MLP + fused mean-pool accumulation
    gemm_kernel<HD, true , false><<<NB, 128>>>(h1, ag1, w1_1, b1_1, a, nullptr, nullptr, nullptr, N);
    gemm_kernel<HD, false, true ><<<NB, 128>>>(a,  nullptr, w2_1, b2_1, nullptr, gids, sums, cnts, N);
    // 6. scorer
    scorer_kernel<<<G, HD>>>(sums, cnts, sw1, sb1, sw2, sb2, out);
}